// round 9
// baseline (speedup 1.0000x reference)
#include <cuda_runtime.h>

// 2-layer LSTM (H=51), B=512, T=512, scalar in, linear head, future=0.
// 128 persistent blocks, BB=4 rows, 640 threads (20 warps = 5/SMSP), 1 barrier/step.
// UNIFORM threads: thread = 4 gates x 1 batch x full-K; weights in padded smem.
// L1: 204 threads, gates complete in-thread (no shuffles). L2: 408 threads
// (x2 matrices), one xor-1 merge. All matmul warps cost 104 FFMA2 -> auto-balanced.
// L2 lags L1 by one step; h double-buffered by parity. tanh.approx activations.

#define H    51
#define HP   56
#define BHP  (4*HP)          // 224
#define TT   512
#define NTH  640
#define NBLK 128
#define NITER 514

// smem offsets in floats (bank-engineered; see analysis)
#define USTRIDE 228          // floats per unit in weight arrays (4 gates x 56 + 4)
#define OFF_W1  0            // base bank 0
#define OFF_W2I 11632        // base bank 16... (mod 32 = 16)
#define OFF_W2H 23264        // (OFF_W2H-OFF_W2I) mod 32 = 16
#define OFF_HB  34912        // h1 parity0/1 [224 each], +4 pad, h2 parity0/1
#define H2OFF   452          // h2 base = OFF_HB+452 (bank offset 4)
#define OFF_X   35840
#define SMEM_FLOATS (OFF_X + 4*TT)
#define SMEM_BYTES  (SMEM_FLOATS*4)

typedef unsigned long long ull;

__device__ __forceinline__ ull fma2(ull a, ull b, ull c) {
    ull d; asm("fma.rn.f32x2 %0, %1, %2, %3;" : "=l"(d) : "l"(a), "l"(b), "l"(c)); return d;
}
__device__ __forceinline__ ull add2(ull a, ull b) {
    ull d; asm("add.rn.f32x2 %0, %1, %2;" : "=l"(d) : "l"(a), "l"(b)); return d;
}
__device__ __forceinline__ float sum2(ull a) {
    float x, y; asm("mov.b64 {%0, %1}, %2;" : "=f"(x), "=f"(y) : "l"(a)); return x + y;
}
__device__ __forceinline__ float tanhap(float x) {
    float y; asm("tanh.approx.f32 %0, %1;" : "=f"(y) : "f"(x)); return y;
}
__device__ __forceinline__ float sigap(float x) {
    return fmaf(0.5f, tanhap(0.5f * x), 0.5f);
}

extern __shared__ float smem[];

__global__ __launch_bounds__(NTH, 1)
void lstm2_kernel(const float* __restrict__ input,
                  const float* __restrict__ W_ih1,
                  const float* __restrict__ W_hh1,
                  const float* __restrict__ b_ih1,
                  const float* __restrict__ b_hh1,
                  const float* __restrict__ W_ih2,
                  const float* __restrict__ W_hh2,
                  const float* __restrict__ b_ih2,
                  const float* __restrict__ b_hh2,
                  const float* __restrict__ W_lin,
                  const float* __restrict__ b_lin,
                  float* __restrict__ out)
{
    const int tid  = threadIdx.x;
    const int lane = tid & 31;
    const int row0 = blockIdx.x * 4;

    float* const h1b  = smem + OFF_HB;
    float* const h2b  = smem + OFF_HB + H2OFF;
    float* const xall = smem + OFF_X;

    // ---- zero whole smem region, then stage ----
    for (int i = tid; i < SMEM_FLOATS; i += NTH) smem[i] = 0.0f;
    __syncthreads();

    // stage weights: [unit][gate][k] -> unit*USTRIDE + gate*56 + k
    for (int idx = tid; idx < 51*4*52; idx += NTH) {
        const int u = idx / 208;
        const int r = idx - u*208;
        const int g = r / 52;
        const int k = r - g*52;
        if (k < 51) {
            const int src = (u + 51*g)*H + k;
            const int dst = u*USTRIDE + g*56 + k;
            smem[OFF_W1  + dst] = W_hh1[src];
            smem[OFF_W2I + dst] = W_ih2[src];
            smem[OFF_W2H + dst] = W_hh2[src];
        }
    }
    for (int i = tid; i < 4*TT; i += NTH) {
        const int b = i >> 9;
        const int t = i & (TT - 1);
        xall[i] = input[(row0 + b)*TT + t];
    }

    // ---- roles ----
    // tid 0..203   : L1, unit = tid>>2, b = tid&3
    // tid 204..211 : out-head (warp 6 lanes 12..19)
    // tid 224..631 : L2, l2 = tid-224: mat = l2&1, b = (l2>>1)&3, unit = l2>>3
    const bool isL1  = (tid < 204);
    const bool isOut = (tid >= 204 && tid < 212);
    const bool isL2  = (tid >= 224 && tid < 632);

    int unit = 0, b = 0, mat = 0;
    if (isL1)      { unit = tid >> 2; b = tid & 3; }
    else if (isL2) { const int l2 = tid - 224; mat = l2 & 1; b = (l2 >> 1) & 3; unit = l2 >> 3; }

    float bz[4] = {0,0,0,0}, wx[4] = {0,0,0,0};
    if (isL1) {
        #pragma unroll
        for (int g = 0; g < 4; ++g) {
            const int r = unit + 51*g;
            bz[g] = b_ih1[r] + b_hh1[r];
            wx[g] = W_ih1[r];
        }
    } else if (isL2 && mat == 0) {
        #pragma unroll
        for (int g = 0; g < 4; ++g) {
            const int r = unit + 51*g;
            bz[g] = b_ih2[r] + b_hh2[r];
        }
    }

    const float* wbase = isL1 ? (smem + OFF_W1 + unit*USTRIDE)
                              : (smem + (mat ? OFF_W2H : OFF_W2I) + unit*USTRIDE);

    // out-head weights (pair: batch = o>>1, half-of-26 = o&1)
    float wo[26]; float blin = 0.0f; int ob = 0, half = 0;
    if (isOut) {
        const int o = tid - 204;
        ob = o >> 1; half = o & 1;
        #pragma unroll
        for (int m = 0; m < 26; ++m) {
            const int j = half*26 + m;
            wo[m] = (j < H) ? W_lin[j] : 0.0f;
        }
        blin = b_lin[0];
    }

    const unsigned pmask = 0x3u << (lane & 30);

    float cst = 0.f;   // c1 (L1) or c2 (L2 mat0)
    __syncthreads();

    for (int t = 0; t < NITER; ++t) {
        const int p = t & 1;
        float* const h1r = h1b + p*BHP;        // h1(t-1)
        float* const h1w = h1b + (p^1)*BHP;    // h1(t)
        float* const h2r = h2b + p*BHP;        // h2(t-2)
        float* const h2w = h2b + (p^1)*BHP;    // h2(t-1)

        if (isL1) {
            if (t < TT) {
                const float* hb = h1r + b*HP;
                ull ax0=0ull, ax1=0ull, ax2=0ull, ax3=0ull;
                ull ay0=0ull, ay1=0ull, ay2=0ull, ay3=0ull;
                #pragma unroll
                for (int j = 0; j < 13; ++j) {
                    const ulonglong2 hv = *reinterpret_cast<const ulonglong2*>(hb + 4*j);
                    const ulonglong2 w0 = *reinterpret_cast<const ulonglong2*>(wbase + 0*56 + 4*j);
                    const ulonglong2 w1 = *reinterpret_cast<const ulonglong2*>(wbase + 1*56 + 4*j);
                    const ulonglong2 w2v= *reinterpret_cast<const ulonglong2*>(wbase + 2*56 + 4*j);
                    const ulonglong2 w3 = *reinterpret_cast<const ulonglong2*>(wbase + 3*56 + 4*j);
                    ax0 = fma2(w0.x, hv.x, ax0);  ay0 = fma2(w0.y, hv.y, ay0);
                    ax1 = fma2(w1.x, hv.x, ax1);  ay1 = fma2(w1.y, hv.y, ay1);
                    ax2 = fma2(w2v.x,hv.x, ax2);  ay2 = fma2(w2v.y,hv.y, ay2);
                    ax3 = fma2(w3.x, hv.x, ax3);  ay3 = fma2(w3.y, hv.y, ay3);
                }
                const float xv = xall[b*TT + t];
                const float zi = fmaf(xv, wx[0], sum2(add2(ax0, ay0)) + bz[0]);
                const float zf = fmaf(xv, wx[1], sum2(add2(ax1, ay1)) + bz[1]);
                const float zg = fmaf(xv, wx[2], sum2(add2(ax2, ay2)) + bz[2]);
                const float zo = fmaf(xv, wx[3], sum2(add2(ax3, ay3)) + bz[3]);
                const float ig = sigap(zi), fg = sigap(zf);
                const float gg = tanhap(zg), og = sigap(zo);
                cst = fmaf(fg, cst, ig*gg);
                h1w[b*HP + unit] = og * tanhap(cst);
            }
        } else if (isL2) {
            if (t >= 1 && t <= TT) {
                const float* hb = (mat ? h2r : h1r) + b*HP;
                ull ax0=0ull, ax1=0ull, ax2=0ull, ax3=0ull;
                ull ay0=0ull, ay1=0ull, ay2=0ull, ay3=0ull;
                #pragma unroll
                for (int j = 0; j < 13; ++j) {
                    const ulonglong2 hv = *reinterpret_cast<const ulonglong2*>(hb + 4*j);
                    const ulonglong2 w0 = *reinterpret_cast<const ulonglong2*>(wbase + 0*56 + 4*j);
                    const ulonglong2 w1 = *reinterpret_cast<const ulonglong2*>(wbase + 1*56 + 4*j);
                    const ulonglong2 w2v= *reinterpret_cast<const ulonglong2*>(wbase + 2*56 + 4*j);
                    const ulonglong2 w3 = *reinterpret_cast<const ulonglong2*>(wbase + 3*56 + 4*j);
                    ax0 = fma2(w0.x, hv.x, ax0);  ay0 = fma2(w0.y, hv.y, ay0);
                    ax1 = fma2(w1.x, hv.x, ax1);  ay1 = fma2(w1.y, hv.y, ay1);
                    ax2 = fma2(w2v.x,hv.x, ax2);  ay2 = fma2(w2v.y,hv.y, ay2);
                    ax3 = fma2(w3.x, hv.x, ax3);  ay3 = fma2(w3.y, hv.y, ay3);
                }
                float z0 = sum2(add2(ax0, ay0));
                float z1 = sum2(add2(ax1, ay1));
                float z2 = sum2(add2(ax2, ay2));
                float z3 = sum2(add2(ax3, ay3));
                z0 += __shfl_xor_sync(pmask, z0, 1);
                z1 += __shfl_xor_sync(pmask, z1, 1);
                z2 += __shfl_xor_sync(pmask, z2, 1);
                z3 += __shfl_xor_sync(pmask, z3, 1);
                if (mat == 0) {
                    const float ig = sigap(z0 + bz[0]), fg = sigap(z1 + bz[1]);
                    const float gg = tanhap(z2 + bz[2]), og = sigap(z3 + bz[3]);
                    cst = fmaf(fg, cst, ig*gg);
                    h2w[b*HP + unit] = og * tanhap(cst);
                }
            }
        } else if (isOut) {
            if (t >= 2) {
                float v = 0.f;
                #pragma unroll
                for (int m = 0; m < 26; ++m)
                    v = fmaf(h2r[ob*HP + half*26 + m], wo[m], v);
                v += __shfl_xor_sync(pmask, v, 1);
                if (half == 0) out[(row0 + ob)*TT + (t - 2)] = v + blin;
            }
        }
        __syncthreads();
    }
}

extern "C" void kernel_launch(void* const* d_in, const int* in_sizes, int n_in,
                              void* d_out, int out_size)
{
    const float* input = (const float*)d_in[0];
    const float* W_ih1 = (const float*)d_in[1];
    const float* W_hh1 = (const float*)d_in[2];
    const float* b_ih1 = (const float*)d_in[3];
    const float* b_hh1 = (const float*)d_in[4];
    const float* W_ih2 = (const float*)d_in[5];
    const float* W_hh2 = (const float*)d_in[6];
    const float* b_ih2 = (const float*)d_in[7];
    const float* b_hh2 = (const float*)d_in[8];
    const float* W_lin = (const float*)d_in[9];
    const float* b_lin = (const float*)d_in[10];
    float* out = (float*)d_out;

    cudaFuncSetAttribute(lstm2_kernel,
                         cudaFuncAttributeMaxDynamicSharedMemorySize, SMEM_BYTES);
    lstm2_kernel<<<NBLK, NTH, SMEM_BYTES>>>(input, W_ih1, W_hh1, b_ih1, b_hh1,
                                            W_ih2, W_hh2, b_ih2, b_hh2,
                                            W_lin, b_lin, out);
}

// round 10
// speedup vs baseline: 1.1832x; 1.1832x over previous
#include <cuda_runtime.h>

// 2-layer LSTM (H=51), B=512, T=512, scalar in, linear head, future=0.
// 128 persistent blocks, BB=4 rows, 384 threads (12 warps = 3/SMSP).
// R8 compute bodies (4 gates x 4 batches x k-half, weights in regs, f32x2,
// tanh.approx, SMSP-balanced 13/13/13/12) + R7 producer/consumer decoupling:
// per SMSP = 1 L1 warp + 2 L2 warps; L1 runs ahead over a depth-2 h1 ring
// gated by FULL/EMPTY named barriers, so L1's FMA burst overlaps L2's tail.

#define H    51
#define HP   56
#define BHP  (4*HP)
#define TT   512
#define NTH  384
#define NBLK 128

#define BAR_F0 1
#define BAR_F1 2
#define BAR_E0 3
#define BAR_E1 4
#define BAR_CNT 384

typedef unsigned long long ull;

__device__ __forceinline__ void bar_sync_n(int id) {
    asm volatile("bar.sync %0, %1;" :: "r"(id), "r"(BAR_CNT) : "memory");
}
__device__ __forceinline__ void bar_arrive_n(int id) {
    asm volatile("bar.arrive %0, %1;" :: "r"(id), "r"(BAR_CNT) : "memory");
}
__device__ __forceinline__ ull fma2(ull a, ull b, ull c) {
    ull d; asm("fma.rn.f32x2 %0, %1, %2, %3;" : "=l"(d) : "l"(a), "l"(b), "l"(c)); return d;
}
__device__ __forceinline__ ull pack2(float lo, float hi) {
    ull d; asm("mov.b64 %0, {%1, %2};" : "=l"(d) : "f"(lo), "f"(hi)); return d;
}
__device__ __forceinline__ float sum2(ull a) {
    float x, y; asm("mov.b64 {%0, %1}, %2;" : "=f"(x), "=f"(y) : "l"(a)); return x + y;
}
__device__ __forceinline__ float tanhap(float x) {
    float y; asm("tanh.approx.f32 %0, %1;" : "=f"(y) : "f"(x)); return y;
}
__device__ __forceinline__ float sigap(float x) {
    return fmaf(0.5f, tanhap(0.5f * x), 0.5f);
}

__global__ __launch_bounds__(NTH, 1)
void lstm2_kernel(const float* __restrict__ input,
                  const float* __restrict__ W_ih1,
                  const float* __restrict__ W_hh1,
                  const float* __restrict__ b_ih1,
                  const float* __restrict__ b_hh1,
                  const float* __restrict__ W_ih2,
                  const float* __restrict__ W_hh2,
                  const float* __restrict__ b_ih2,
                  const float* __restrict__ b_hh2,
                  const float* __restrict__ W_lin,
                  const float* __restrict__ b_lin,
                  float* __restrict__ out)
{
    __shared__ __align__(16) float hbuf[2*BHP + 8 + 2*BHP];
    __shared__ float xall[4*TT];

    float* const h1b = hbuf;
    float* const h2b = hbuf + 2*BHP + 8;

    const int tid  = threadIdx.x;
    const int lane = tid & 31;
    const int wid  = tid >> 5;
    const int row0 = blockIdx.x * 4;

    const unsigned pmask = 0x3u << (lane & 30);
    const unsigned qmask = 0xFu << (lane & 28);

    // ---- init smem ----
    for (int i = tid; i < 2*BHP + 8 + 2*BHP; i += NTH) hbuf[i] = 0.0f;
    for (int i = tid; i < 4*TT; i += NTH) {
        const int b = i >> 9;
        const int t = i & (TT - 1);
        xall[i] = input[(row0 + b)*TT + t];
    }

    if (wid < 4) {
        // =============== L1 PRODUCER (warps 0-3, one per SMSP) ===============
        const int s1    = wid;                 // SMSP
        const int ubase = 13 * s1;
        const int P1    = (s1 < 3) ? 13 : 12;
        const bool act  = (lane < 2 * P1);
        const int unit  = ubase + (lane >> 1);
        const int ks    = lane & 1;

        ull w2[4][14];
        float bz[4] = {0,0,0,0}, wx[4] = {0,0,0,0};
        if (act) {
            #pragma unroll
            for (int g = 0; g < 4; ++g) {
                const int r = unit + 51*g;
                #pragma unroll
                for (int m = 0; m < 14; ++m) {
                    const int k = ks*28 + 2*m;
                    const float lo = (k   < H) ? W_hh1[r*H + k]     : 0.0f;
                    const float hi = (k+1 < H) ? W_hh1[r*H + k + 1] : 0.0f;
                    w2[g][m] = pack2(lo, hi);
                }
                bz[g] = b_ih1[r] + b_hh1[r];
                wx[g] = W_ih1[r];
            }
        }
        float c1[2] = {0.f, 0.f};

        __syncthreads();   // init visibility (all 384)

        for (int t = 0; t < 513; ++t) {
            const int s = t & 1;
            bar_sync_n(s ? BAR_E1 : BAR_E0);        // L2 done reading h1(t-2)
            if (act && t < TT) {
                const float* h1r = h1b + (s^1)*BHP; // h1(t-1)
                float*       h1w = h1b + s*BHP;     // h1(t)
                ull acc[4][4];
                #pragma unroll
                for (int g = 0; g < 4; ++g)
                    { acc[g][0]=0ull; acc[g][1]=0ull; acc[g][2]=0ull; acc[g][3]=0ull; }
                const float* hp = h1r + ks*28;
                #pragma unroll
                for (int j = 0; j < 7; ++j) {
                    const ulonglong2 u0 = *reinterpret_cast<const ulonglong2*>(hp + 0*HP + 4*j);
                    const ulonglong2 u1 = *reinterpret_cast<const ulonglong2*>(hp + 1*HP + 4*j);
                    const ulonglong2 u2 = *reinterpret_cast<const ulonglong2*>(hp + 2*HP + 4*j);
                    const ulonglong2 u3 = *reinterpret_cast<const ulonglong2*>(hp + 3*HP + 4*j);
                    #pragma unroll
                    for (int g = 0; g < 4; ++g) {
                        acc[g][0] = fma2(w2[g][2*j],   u0.x, acc[g][0]);
                        acc[g][0] = fma2(w2[g][2*j+1], u0.y, acc[g][0]);
                        acc[g][1] = fma2(w2[g][2*j],   u1.x, acc[g][1]);
                        acc[g][1] = fma2(w2[g][2*j+1], u1.y, acc[g][1]);
                        acc[g][2] = fma2(w2[g][2*j],   u2.x, acc[g][2]);
                        acc[g][2] = fma2(w2[g][2*j+1], u2.y, acc[g][2]);
                        acc[g][3] = fma2(w2[g][2*j],   u3.x, acc[g][3]);
                        acc[g][3] = fma2(w2[g][2*j+1], u3.y, acc[g][3]);
                    }
                }
                float fin[4][2];
                #pragma unroll
                for (int g = 0; g < 4; ++g)
                    #pragma unroll
                    for (int lb = 0; lb < 2; ++lb) {
                        const float mine  = sum2(ks ? acc[g][2+lb] : acc[g][lb]);
                        const float other = sum2(ks ? acc[g][lb]   : acc[g][2+lb]);
                        fin[g][lb] = mine + __shfl_xor_sync(pmask, other, 1);
                    }
                #pragma unroll
                for (int lb = 0; lb < 2; ++lb) {
                    const int b = 2*ks + lb;
                    const float xv = xall[b*TT + t];
                    const float zi = fmaf(xv, wx[0], fin[0][lb] + bz[0]);
                    const float zf = fmaf(xv, wx[1], fin[1][lb] + bz[1]);
                    const float zg = fmaf(xv, wx[2], fin[2][lb] + bz[2]);
                    const float zo = fmaf(xv, wx[3], fin[3][lb] + bz[3]);
                    const float ig = sigap(zi), fg = sigap(zf);
                    const float gg = tanhap(zg), og = sigap(zo);
                    c1[lb] = fmaf(fg, c1[lb], ig*gg);
                    h1w[b*HP + unit] = og * tanhap(c1[lb]);
                }
            }
            bar_arrive_n(s ? BAR_F1 : BAR_F0);      // h1(t) published
        }
    } else {
        // =============== L2 CONSUMER (warps 4-11, two per SMSP) ===============
        const int s2   = wid & 3;                  // SMSP
        const int sub  = (wid - 4) >> 2;           // 0: first 7 quads, 1: rest
        const int qb   = 13 * s2;
        const int NQ   = (s2 < 3) ? 13 : 12;
        const int nq   = sub ? (NQ - 7) : 7;       // quads in this warp
        const bool act = (lane < 4 * nq);
        const int unit = qb + sub*7 + (lane >> 2);
        const int mat  = (lane >> 1) & 1;
        const int ks   = lane & 1;
        const bool isOut = (wid == 11) && (lane >= 20 && lane < 28);

        ull w2[4][14];
        float bz[4] = {0,0,0,0};
        if (act) {
            const float* W = mat ? W_hh2 : W_ih2;
            #pragma unroll
            for (int g = 0; g < 4; ++g) {
                const int r = unit + 51*g;
                #pragma unroll
                for (int m = 0; m < 14; ++m) {
                    const int k = ks*28 + 2*m;
                    const float lo = (k   < H) ? W[r*H + k]     : 0.0f;
                    const float hi = (k+1 < H) ? W[r*H + k + 1] : 0.0f;
                    w2[g][m] = pack2(lo, hi);
                }
                bz[g] = b_ih2[r] + b_hh2[r];
            }
        }
        float c2 = 0.f;

        float wo[26]; float blin = 0.0f; int ob = 0, half = 0;
        if (isOut) {
            const int o = lane - 20;
            ob = o >> 1; half = o & 1;
            #pragma unroll
            for (int m = 0; m < 26; ++m) {
                const int j = half*26 + m;
                wo[m] = (j < H) ? W_lin[j] : 0.0f;
            }
            blin = b_lin[0];
        }

        __syncthreads();   // init visibility (all 384)

        // pre-seed EMPTY so L1's first two waits pass
        bar_arrive_n(BAR_E0);
        bar_arrive_n(BAR_E1);

        for (int t = 0; t < 513; ++t) {
            const int s = t & 1;
            bar_sync_n(s ? BAR_F1 : BAR_F0);        // h1(t) ready
            if (act && t < TT) {
                const float* h1r = h1b + s*BHP;     // h1(t)
                const float* h2r = h2b + (s^1)*BHP; // h2(t-1)
                float*       h2w = h2b + s*BHP;     // h2(t)
                ull acc[4][4];
                #pragma unroll
                for (int g = 0; g < 4; ++g)
                    { acc[g][0]=0ull; acc[g][1]=0ull; acc[g][2]=0ull; acc[g][3]=0ull; }
                const float* hp = (mat ? h2r : h1r) + ks*28;
                #pragma unroll
                for (int j = 0; j < 7; ++j) {
                    const ulonglong2 u0 = *reinterpret_cast<const ulonglong2*>(hp + 0*HP + 4*j);
                    const ulonglong2 u1 = *reinterpret_cast<const ulonglong2*>(hp + 1*HP + 4*j);
                    const ulonglong2 u2 = *reinterpret_cast<const ulonglong2*>(hp + 2*HP + 4*j);
                    const ulonglong2 u3 = *reinterpret_cast<const ulonglong2*>(hp + 3*HP + 4*j);
                    #pragma unroll
                    for (int g = 0; g < 4; ++g) {
                        acc[g][0] = fma2(w2[g][2*j],   u0.x, acc[g][0]);
                        acc[g][0] = fma2(w2[g][2*j+1], u0.y, acc[g][0]);
                        acc[g][1] = fma2(w2[g][2*j],   u1.x, acc[g][1]);
                        acc[g][1] = fma2(w2[g][2*j+1], u1.y, acc[g][1]);
                        acc[g][2] = fma2(w2[g][2*j],   u2.x, acc[g][2]);
                        acc[g][2] = fma2(w2[g][2*j+1], u2.y, acc[g][2]);
                        acc[g][3] = fma2(w2[g][2*j],   u3.x, acc[g][3]);
                        acc[g][3] = fma2(w2[g][2*j+1], u3.y, acc[g][3]);
                    }
                }
                float fin1[4][2];
                #pragma unroll
                for (int g = 0; g < 4; ++g)
                    #pragma unroll
                    for (int lb = 0; lb < 2; ++lb) {
                        const float mine  = sum2(ks ? acc[g][2+lb] : acc[g][lb]);
                        const float other = sum2(ks ? acc[g][lb]   : acc[g][2+lb]);
                        fin1[g][lb] = mine + __shfl_xor_sync(pmask, other, 1);
                    }
                const int b = 2*ks + mat;
                float zf4[4];
                #pragma unroll
                for (int g = 0; g < 4; ++g) {
                    const float mine  = mat ? fin1[g][1] : fin1[g][0];
                    const float other = mat ? fin1[g][0] : fin1[g][1];
                    zf4[g] = mine + __shfl_xor_sync(qmask, other, 2) + bz[g];
                }
                const float ig = sigap(zf4[0]), fg = sigap(zf4[1]);
                const float gg = tanhap(zf4[2]), og = sigap(zf4[3]);
                c2 = fmaf(fg, c2, ig*gg);
                h2w[b*HP + unit] = og * tanhap(c2);
            }
            if (isOut && t >= 1) {
                const float* h2r = h2b + (s^1)*BHP; // h2(t-1)
                float v = 0.f;
                #pragma unroll
                for (int m = 0; m < 26; ++m)
                    v = fmaf(h2r[ob*HP + half*26 + m], wo[m], v);
                v += __shfl_xor_sync(pmask, v, 1);
                if (half == 0) out[(row0 + ob)*TT + (t - 1)] = v + blin;
            }
            bar_arrive_n(s ? BAR_E1 : BAR_E0);      // h1(t) consumed
        }
    }
}

extern "C" void kernel_launch(void* const* d_in, const int* in_sizes, int n_in,
                              void* d_out, int out_size)
{
    const float* input = (const float*)d_in[0];
    const float* W_ih1 = (const float*)d_in[1];
    const float* W_hh1 = (const float*)d_in[2];
    const float* b_ih1 = (const float*)d_in[3];
    const float* b_hh1 = (const float*)d_in[4];
    const float* W_ih2 = (const float*)d_in[5];
    const float* W_hh2 = (const float*)d_in[6];
    const float* b_ih2 = (const float*)d_in[7];
    const float* b_hh2 = (const float*)d_in[8];
    const float* W_lin = (const float*)d_in[9];
    const float* b_lin = (const float*)d_in[10];
    float* out = (float*)d_out;

    lstm2_kernel<<<NBLK, NTH>>>(input, W_ih1, W_hh1, b_ih1, b_hh1,
                                W_ih2, W_hh2, b_ih2, b_hh2,
                                W_lin, b_lin, out);
}

// round 11
// speedup vs baseline: 1.2801x; 1.0819x over previous
#include <cuda_runtime.h>

// 2-layer LSTM (H=51), B=512, T=512, scalar in, linear head, future=0.
// 128 persistent blocks, BB=4 rows, 384 threads (12 warps = 3/SMSP).
// THREE decoupled pipeline stages, 1 warp per SMSP each:
//   G1 (warps 0-3):  z1 = Whh1*h1(t-1) + x*Wih1 + b1 -> combine -> h1(t)
//   G2 (warps 4-7):  zih = Wih2*h1(t)                -> smem z-ring
//   G3 (warps 8-11): zhh = Whh2*h2(t-1); z = zih+zhh+b2 -> combine -> h2(t); out head
// Named-barrier rings (depth 2): F1/E1 for h1 (G1<->G2), FZ/EZ for z (G2<->G3).
// Per-thread: 4 gates x 4 batches x k-half, weights in regs (f32x2), tanh.approx.

#define H    51
#define HP   56
#define BHP  (4*HP)
#define TT   512
#define NTH  384
#define NBLK 128
#define NIT  513

// barrier ids: parity0 = base, parity1 = base+4
#define BF1 1
#define BE1 2
#define BFZ 3
#define BEZ 4
#define BCNT 256

#define ZSLOT 1020           // floats per z-ring slot: (2u+ks)<102, stride 10

typedef unsigned long long ull;

__device__ __forceinline__ void bar_sync_n(int id) {
    asm volatile("bar.sync %0, %1;" :: "r"(id), "r"(BCNT) : "memory");
}
__device__ __forceinline__ void bar_arrive_n(int id) {
    asm volatile("bar.arrive %0, %1;" :: "r"(id), "r"(BCNT) : "memory");
}
__device__ __forceinline__ ull fma2(ull a, ull b, ull c) {
    ull d; asm("fma.rn.f32x2 %0, %1, %2, %3;" : "=l"(d) : "l"(a), "l"(b), "l"(c)); return d;
}
__device__ __forceinline__ ull pack2(float lo, float hi) {
    ull d; asm("mov.b64 %0, {%1, %2};" : "=l"(d) : "f"(lo), "f"(hi)); return d;
}
__device__ __forceinline__ float sum2(ull a) {
    float x, y; asm("mov.b64 {%0, %1}, %2;" : "=f"(x), "=f"(y) : "l"(a)); return x + y;
}
__device__ __forceinline__ float tanhap(float x) {
    float y; asm("tanh.approx.f32 %0, %1;" : "=f"(y) : "f"(x)); return y;
}
__device__ __forceinline__ float sigap(float x) {
    return fmaf(0.5f, tanhap(0.5f * x), 0.5f);
}

__global__ __launch_bounds__(NTH, 1)
void lstm2_kernel(const float* __restrict__ input,
                  const float* __restrict__ W_ih1,
                  const float* __restrict__ W_hh1,
                  const float* __restrict__ b_ih1,
                  const float* __restrict__ b_hh1,
                  const float* __restrict__ W_ih2,
                  const float* __restrict__ W_hh2,
                  const float* __restrict__ b_ih2,
                  const float* __restrict__ b_hh2,
                  const float* __restrict__ W_lin,
                  const float* __restrict__ b_lin,
                  float* __restrict__ out)
{
    __shared__ __align__(16) float hbuf[2*BHP + 8 + 2*BHP];
    __shared__ __align__(8)  float zring[2*ZSLOT];
    __shared__ float xall[4*TT];

    float* const h1b = hbuf;
    float* const h2b = hbuf + 2*BHP + 8;

    const int tid  = threadIdx.x;
    const int lane = tid & 31;
    const int wid  = tid >> 5;
    const int grp  = wid >> 2;      // 0=G1, 1=G2, 2=G3
    const int s    = wid & 3;       // SMSP
    const int row0 = blockIdx.x * 4;

    const unsigned pmask = 0x3u << (lane & 30);

    for (int i = tid; i < 2*BHP + 8 + 2*BHP; i += NTH) hbuf[i] = 0.0f;
    for (int i = tid; i < 2*ZSLOT; i += NTH) zring[i] = 0.0f;
    for (int i = tid; i < 4*TT; i += NTH) {
        const int b = i >> 9;
        const int t = i & (TT - 1);
        xall[i] = input[(row0 + b)*TT + t];
    }

    const int ubase = 13 * s;
    const int NU    = (s < 3) ? 13 : 12;
    const bool act  = (lane < 2 * NU);
    const int unit  = ubase + (lane >> 1);
    const int ks    = lane & 1;
    const bool isOut = (grp == 2) && (s == 3) && (lane >= 24);

    ull w2[4][14];
    float bz[4] = {0,0,0,0}, wx[4] = {0,0,0,0};
    if (act) {
        const float* W = (grp == 0) ? W_hh1 : ((grp == 1) ? W_ih2 : W_hh2);
        #pragma unroll
        for (int g = 0; g < 4; ++g) {
            const int r = unit + 51*g;
            #pragma unroll
            for (int m = 0; m < 14; ++m) {
                const int k = ks*28 + 2*m;
                const float lo = (k   < H) ? W[r*H + k]     : 0.0f;
                const float hi = (k+1 < H) ? W[r*H + k + 1] : 0.0f;
                w2[g][m] = pack2(lo, hi);
            }
            if (grp == 0) { bz[g] = b_ih1[r] + b_hh1[r]; wx[g] = W_ih1[r]; }
            if (grp == 2) { bz[g] = b_ih2[r] + b_hh2[r]; }
        }
    }

    float wo[26]; float blin = 0.0f; int ob = 0, half = 0;
    if (isOut) {
        const int o = lane - 24;
        ob = o >> 1; half = o & 1;
        #pragma unroll
        for (int m = 0; m < 26; ++m) {
            const int j = half*26 + m;
            wo[m] = (j < H) ? W_lin[j] : 0.0f;
        }
        blin = b_lin[0];
    }

    float c1[2] = {0.f, 0.f};
    float c2[2] = {0.f, 0.f};
    const int zb = 2*unit + ks;

    __syncthreads();

    if (grp == 0) {
        // ================= G1 =================
        for (int t = 0; t < NIT; ++t) {
            const int sl = t & 1;
            bar_sync_n(sl ? (BE1 + 4) : BE1);
            if (act && t < TT) {
                const float* h1r = h1b + (sl^1)*BHP;
                float*       h1w = h1b + sl*BHP;
                ull acc[4][4];
                #pragma unroll
                for (int g = 0; g < 4; ++g)
                    { acc[g][0]=0ull; acc[g][1]=0ull; acc[g][2]=0ull; acc[g][3]=0ull; }
                const float* hp = h1r + ks*28;
                #pragma unroll
                for (int j = 0; j < 7; ++j) {
                    const ulonglong2 u0 = *reinterpret_cast<const ulonglong2*>(hp + 0*HP + 4*j);
                    const ulonglong2 u1 = *reinterpret_cast<const ulonglong2*>(hp + 1*HP + 4*j);
                    const ulonglong2 u2 = *reinterpret_cast<const ulonglong2*>(hp + 2*HP + 4*j);
                    const ulonglong2 u3 = *reinterpret_cast<const ulonglong2*>(hp + 3*HP + 4*j);
                    #pragma unroll
                    for (int g = 0; g < 4; ++g) {
                        acc[g][0] = fma2(w2[g][2*j],   u0.x, acc[g][0]);
                        acc[g][0] = fma2(w2[g][2*j+1], u0.y, acc[g][0]);
                        acc[g][1] = fma2(w2[g][2*j],   u1.x, acc[g][1]);
                        acc[g][1] = fma2(w2[g][2*j+1], u1.y, acc[g][1]);
                        acc[g][2] = fma2(w2[g][2*j],   u2.x, acc[g][2]);
                        acc[g][2] = fma2(w2[g][2*j+1], u2.y, acc[g][2]);
                        acc[g][3] = fma2(w2[g][2*j],   u3.x, acc[g][3]);
                        acc[g][3] = fma2(w2[g][2*j+1], u3.y, acc[g][3]);
                    }
                }
                float fin[4][2];
                #pragma unroll
                for (int g = 0; g < 4; ++g)
                    #pragma unroll
                    for (int lb = 0; lb < 2; ++lb) {
                        const float mine  = sum2(ks ? acc[g][2+lb] : acc[g][lb]);
                        const float other = sum2(ks ? acc[g][lb]   : acc[g][2+lb]);
                        fin[g][lb] = mine + __shfl_xor_sync(pmask, other, 1);
                    }
                #pragma unroll
                for (int lb = 0; lb < 2; ++lb) {
                    const int b = 2*ks + lb;
                    const float xv = xall[b*TT + t];
                    const float zi = fmaf(xv, wx[0], fin[0][lb] + bz[0]);
                    const float zf = fmaf(xv, wx[1], fin[1][lb] + bz[1]);
                    const float zg = fmaf(xv, wx[2], fin[2][lb] + bz[2]);
                    const float zo = fmaf(xv, wx[3], fin[3][lb] + bz[3]);
                    const float ig = sigap(zi), fg = sigap(zf);
                    const float gg = tanhap(zg), og = sigap(zo);
                    c1[lb] = fmaf(fg, c1[lb], ig*gg);
                    h1w[b*HP + unit] = og * tanhap(c1[lb]);
                }
            }
            bar_arrive_n(sl ? (BF1 + 4) : BF1);
        }
    } else if (grp == 1) {
        // ================= G2 =================
        bar_arrive_n(BE1);
        bar_arrive_n(BE1 + 4);
        for (int t = 0; t < NIT; ++t) {
            const int sl = t & 1;
            bar_sync_n(sl ? (BF1 + 4) : BF1);
            bar_sync_n(sl ? (BEZ + 4) : BEZ);
            if (act && t < TT) {
                const float* h1r = h1b + sl*BHP;
                ull acc[4][4];
                #pragma unroll
                for (int g = 0; g < 4; ++g)
                    { acc[g][0]=0ull; acc[g][1]=0ull; acc[g][2]=0ull; acc[g][3]=0ull; }
                const float* hp = h1r + ks*28;
                #pragma unroll
                for (int j = 0; j < 7; ++j) {
                    const ulonglong2 u0 = *reinterpret_cast<const ulonglong2*>(hp + 0*HP + 4*j);
                    const ulonglong2 u1 = *reinterpret_cast<const ulonglong2*>(hp + 1*HP + 4*j);
                    const ulonglong2 u2 = *reinterpret_cast<const ulonglong2*>(hp + 2*HP + 4*j);
                    const ulonglong2 u3 = *reinterpret_cast<const ulonglong2*>(hp + 3*HP + 4*j);
                    #pragma unroll
                    for (int g = 0; g < 4; ++g) {
                        acc[g][0] = fma2(w2[g][2*j],   u0.x, acc[g][0]);
                        acc[g][0] = fma2(w2[g][2*j+1], u0.y, acc[g][0]);
                        acc[g][1] = fma2(w2[g][2*j],   u1.x, acc[g][1]);
                        acc[g][1] = fma2(w2[g][2*j+1], u1.y, acc[g][1]);
                        acc[g][2] = fma2(w2[g][2*j],   u2.x, acc[g][2]);
                        acc[g][2] = fma2(w2[g][2*j+1], u2.y, acc[g][2]);
                        acc[g][3] = fma2(w2[g][2*j],   u3.x, acc[g][3]);
                        acc[g][3] = fma2(w2[g][2*j+1], u3.y, acc[g][3]);
                    }
                }
                float* zw = zring + sl*ZSLOT + zb*10;
                #pragma unroll
                for (int g = 0; g < 4; ++g) {
                    const float m0 = sum2(ks ? acc[g][2] : acc[g][0]);
                    const float o0 = sum2(ks ? acc[g][0] : acc[g][2]);
                    const float m1 = sum2(ks ? acc[g][3] : acc[g][1]);
                    const float o1 = sum2(ks ? acc[g][1] : acc[g][3]);
                    float2 zv;
                    zv.x = m0 + __shfl_xor_sync(pmask, o0, 1);
                    zv.y = m1 + __shfl_xor_sync(pmask, o1, 1);
                    *reinterpret_cast<float2*>(zw + 2*g) = zv;
                }
            }
            bar_arrive_n(sl ? (BFZ + 4) : BFZ);
            bar_arrive_n(sl ? (BE1 + 4) : BE1);
        }
    } else {
        // ================= G3 =================
        bar_arrive_n(BEZ);
        bar_arrive_n(BEZ + 4);
        for (int t = 0; t < NIT; ++t) {
            const int sl = t & 1;
            bar_sync_n(sl ? (BFZ + 4) : BFZ);
            if (act && t < TT) {
                const float* h2r = h2b + (sl^1)*BHP;
                float*       h2w = h2b + sl*BHP;
                ull acc[4][4];
                #pragma unroll
                for (int g = 0; g < 4; ++g)
                    { acc[g][0]=0ull; acc[g][1]=0ull; acc[g][2]=0ull; acc[g][3]=0ull; }
                const float* hp = h2r + ks*28;
                #pragma unroll
                for (int j = 0; j < 7; ++j) {
                    const ulonglong2 u0 = *reinterpret_cast<const ulonglong2*>(hp + 0*HP + 4*j);
                    const ulonglong2 u1 = *reinterpret_cast<const ulonglong2*>(hp + 1*HP + 4*j);
                    const ulonglong2 u2 = *reinterpret_cast<const ulonglong2*>(hp + 2*HP + 4*j);
                    const ulonglong2 u3 = *reinterpret_cast<const ulonglong2*>(hp + 3*HP + 4*j);
                    #pragma unroll
                    for (int g = 0; g < 4; ++g) {
                        acc[g][0] = fma2(w2[g][2*j],   u0.x, acc[g][0]);
                        acc[g][0] = fma2(w2[g][2*j+1], u0.y, acc[g][0]);
                        acc[g][1] = fma2(w2[g][2*j],   u1.x, acc[g][1]);
                        acc[g][1] = fma2(w2[g][2*j+1], u1.y, acc[g][1]);
                        acc[g][2] = fma2(w2[g][2*j],   u2.x, acc[g][2]);
                        acc[g][2] = fma2(w2[g][2*j+1], u2.y, acc[g][2]);
                        acc[g][3] = fma2(w2[g][2*j],   u3.x, acc[g][3]);
                        acc[g][3] = fma2(w2[g][2*j+1], u3.y, acc[g][3]);
                    }
                }
                float fin[4][2];
                #pragma unroll
                for (int g = 0; g < 4; ++g)
                    #pragma unroll
                    for (int lb = 0; lb < 2; ++lb) {
                        const float mine  = sum2(ks ? acc[g][2+lb] : acc[g][lb]);
                        const float other = sum2(ks ? acc[g][lb]   : acc[g][2+lb]);
                        fin[g][lb] = mine + __shfl_xor_sync(pmask, other, 1);
                    }
                const float* zr = zring + sl*ZSLOT + zb*10;
                float2 zv[4];
                #pragma unroll
                for (int g = 0; g < 4; ++g)
                    zv[g] = *reinterpret_cast<const float2*>(zr + 2*g);
                #pragma unroll
                for (int lb = 0; lb < 2; ++lb) {
                    const int b = 2*ks + lb;
                    const float zi = fin[0][lb] + (lb ? zv[0].y : zv[0].x) + bz[0];
                    const float zf = fin[1][lb] + (lb ? zv[1].y : zv[1].x) + bz[1];
                    const float zg = fin[2][lb] + (lb ? zv[2].y : zv[2].x) + bz[2];
                    const float zo = fin[3][lb] + (lb ? zv[3].y : zv[3].x) + bz[3];
                    const float ig = sigap(zi), fg = sigap(zf);
                    const float gg = tanhap(zg), og = sigap(zo);
                    c2[lb] = fmaf(fg, c2[lb], ig*gg);
                    h2w[b*HP + unit] = og * tanhap(c2[lb]);
                }
            }
            if (isOut && t >= 1 && t <= TT) {
                const float* h2p = h2b + ((t-1)&1)*BHP;
                float v = 0.f;
                #pragma unroll
                for (int m = 0; m < 26; ++m)
                    v = fmaf(h2p[ob*HP + half*26 + m], wo[m], v);
                v += __shfl_xor_sync(pmask, v, 1);
                if (half == 0) out[(row0 + ob)*TT + (t - 1)] = v + blin;
            }
            bar_arrive_n(sl ? (BEZ + 4) : BEZ);
        }
    }
}

extern "C" void kernel_launch(void* const* d_in, const int* in_sizes, int n_in,
                              void* d_out, int out_size)
{
    const float* input = (const float*)d_in[0];
    const float* W_ih1 = (const float*)d_in[1];
    const float* W_hh1 = (const float*)d_in[2];
    const float* b_ih1 = (const float*)d_in[3];
    const float* b_hh1 = (const float*)d_in[4];
    const float* W_ih2 = (const float*)d_in[5];
    const float* W_hh2 = (const float*)d_in[6];
    const float* b_ih2 = (const float*)d_in[7];
    const float* b_hh2 = (const float*)d_in[8];
    const float* W_lin = (const float*)d_in[9];
    const float* b_lin = (const float*)d_in[10];
    float* out = (float*)d_out;

    lstm2_kernel<<<NBLK, NTH>>>(input, W_ih1, W_hh1, b_ih1, b_hh1,
                                W_ih2, W_hh2, b_ih2, b_hh2,
                                W_lin, b_lin, out);
}